// round 3
// baseline (speedup 1.0000x reference)
#include <cuda_runtime.h>
#include <math.h>

#define E_DIM  768
#define N_HEAD 12
#define D_HEAD 64
#define BATCH  4
#define SEQ    2048
#define M_ROWS (BATCH * SEQ)   // 8192

// Scratch (device globals: allocation-free per harness rules)
__device__ float g_Q[BATCH * N_HEAD * SEQ * D_HEAD];
__device__ float g_K[BATCH * N_HEAD * SEQ * D_HEAD];
__device__ float g_V[BATCH * N_HEAD * SEQ * D_HEAD];
__device__ float g_ctx[M_ROWS * E_DIM];

// ---------------------------------------------------------------------------
// C[m,n] = sum_k A[m,k] * W[n,k]
// mode 0: scatter into [B,H,S,D] layout (QKV projections)
// mode 1: out[m*E+n] = acc + resid[m*E+n] (output projection + residual)
// 64x64 tile, 16-wide K panels, 256 threads, 4x4 microtile per thread.
// ---------------------------------------------------------------------------
__global__ __launch_bounds__(256) void gemm_nt_kernel(
    const float* __restrict__ A, const float* __restrict__ W,
    const float* __restrict__ resid, float* __restrict__ out, int mode)
{
    __shared__ __align__(16) float As[16][68];
    __shared__ __align__(16) float Ws[16][68];

    const int tid  = threadIdx.x;
    const int row0 = blockIdx.y * 64;
    const int col0 = blockIdx.x * 64;
    const int lrow = tid >> 2;          // 0..63
    const int kv   = (tid & 3) * 4;     // 0,4,8,12
    const int ty   = tid >> 4;          // 0..15
    const int tx   = tid & 15;          // 0..15

    float acc[4][4];
#pragma unroll
    for (int i = 0; i < 4; i++)
#pragma unroll
        for (int j = 0; j < 4; j++) acc[i][j] = 0.f;

    for (int k0 = 0; k0 < E_DIM; k0 += 16) {
        float4 av = *(const float4*)&A[(size_t)(row0 + lrow) * E_DIM + k0 + kv];
        float4 wv = *(const float4*)&W[(size_t)(col0 + lrow) * E_DIM + k0 + kv];
        __syncthreads();
        As[kv + 0][lrow] = av.x; As[kv + 1][lrow] = av.y;
        As[kv + 2][lrow] = av.z; As[kv + 3][lrow] = av.w;
        Ws[kv + 0][lrow] = wv.x; Ws[kv + 1][lrow] = wv.y;
        Ws[kv + 2][lrow] = wv.z; Ws[kv + 3][lrow] = wv.w;
        __syncthreads();
#pragma unroll
        for (int kk = 0; kk < 16; kk++) {
            float4 a = *(const float4*)&As[kk][ty * 4];
            float4 b = *(const float4*)&Ws[kk][tx * 4];
            float ar[4] = {a.x, a.y, a.z, a.w};
            float br[4] = {b.x, b.y, b.z, b.w};
#pragma unroll
            for (int i = 0; i < 4; i++)
#pragma unroll
                for (int j = 0; j < 4; j++)
                    acc[i][j] = fmaf(ar[i], br[j], acc[i][j]);
        }
    }

    if (mode == 0) {
#pragma unroll
        for (int i = 0; i < 4; i++) {
            int m = row0 + ty * 4 + i;
            int b = m >> 11;            // / SEQ
            int s = m & (SEQ - 1);
#pragma unroll
            for (int j = 0; j < 4; j++) {
                int n = col0 + tx * 4 + j;
                int h = n >> 6;         // / D_HEAD
                int d = n & (D_HEAD - 1);
                out[(((size_t)b * N_HEAD + h) * SEQ + s) * D_HEAD + d] = acc[i][j];
            }
        }
    } else {
#pragma unroll
        for (int i = 0; i < 4; i++) {
            int m = row0 + ty * 4 + i;
#pragma unroll
            for (int j = 0; j < 4; j++) {
                int n = col0 + tx * 4 + j;
                size_t idx = (size_t)m * E_DIM + n;
                out[idx] = acc[i][j] + resid[idx];
            }
        }
    }
}

// ---------------------------------------------------------------------------
// Flash attention: one thread per query row, 128 queries per block.
// K/V streamed through shared in 64-row tiles; online softmax in registers.
// scores = QK^T / 8, mask (int32, nonzero == True) -> -1e9.
// Writes context in [B, S, E] layout (head dims re-interleaved).
// ---------------------------------------------------------------------------
__global__ __launch_bounds__(128) void attn_kernel(
    const float* __restrict__ Q, const float* __restrict__ K,
    const float* __restrict__ V, const int* __restrict__ mask,
    float* __restrict__ ctx)
{
    __shared__ __align__(16) float Ks[64][64];
    __shared__ __align__(16) float Vs[64][64];

    const int tid = threadIdx.x;
    const int h   = blockIdx.y;
    const int b   = blockIdx.z;
    const int q   = blockIdx.x * 128 + tid;
    const int bh  = b * N_HEAD + h;

    const float* qptr  = Q + ((size_t)bh * SEQ + q) * D_HEAD;
    const float* Kbase = K + (size_t)bh * SEQ * D_HEAD;
    const float* Vbase = V + (size_t)bh * SEQ * D_HEAD;
    const int* mrow = mask + ((size_t)b * SEQ + q) * SEQ;

    float qreg[D_HEAD];
#pragma unroll
    for (int i = 0; i < 16; i++) {
        float4 v = *(const float4*)(qptr + i * 4);
        qreg[i * 4 + 0] = v.x; qreg[i * 4 + 1] = v.y;
        qreg[i * 4 + 2] = v.z; qreg[i * 4 + 3] = v.w;
    }

    float m = -1e30f, l = 0.f;
    float oacc[D_HEAD];
#pragma unroll
    for (int d = 0; d < D_HEAD; d++) oacc[d] = 0.f;

    for (int kt = 0; kt < SEQ; kt += 64) {
        __syncthreads();
#pragma unroll
        for (int t = 0; t < 8; t++) {
            int idx = tid + t * 128;        // 0..1023
            int r = idx >> 4;
            int c = (idx & 15) << 2;
            *(float4*)&Ks[r][c] = *(const float4*)&Kbase[(size_t)(kt + r) * D_HEAD + c];
            *(float4*)&Vs[r][c] = *(const float4*)&Vbase[(size_t)(kt + r) * D_HEAD + c];
        }
        __syncthreads();

#pragma unroll
        for (int c16 = 0; c16 < 4; c16++) {     // 16-key chunks
            int mv[16];
#pragma unroll
            for (int t = 0; t < 4; t++) {
                int4 u = *(const int4*)&mrow[kt + c16 * 16 + t * 4];
                mv[t * 4 + 0] = u.x; mv[t * 4 + 1] = u.y;
                mv[t * 4 + 2] = u.z; mv[t * 4 + 3] = u.w;
            }

            float s[16];
            float tmax = -1e30f;
#pragma unroll
            for (int kk = 0; kk < 16; kk++) {
                int krow = c16 * 16 + kk;
                float d0 = 0.f, d1 = 0.f;
#pragma unroll
                for (int d4 = 0; d4 < 16; d4 += 2) {
                    float4 k0 = *(const float4*)&Ks[krow][d4 * 4];
                    float4 k1 = *(const float4*)&Ks[krow][d4 * 4 + 4];
                    d0 = fmaf(qreg[d4 * 4 + 0], k0.x, d0);
                    d0 = fmaf(qreg[d4 * 4 + 1], k0.y, d0);
                    d0 = fmaf(qreg[d4 * 4 + 2], k0.z, d0);
                    d0 = fmaf(qreg[d4 * 4 + 3], k0.w, d0);
                    d1 = fmaf(qreg[d4 * 4 + 4], k1.x, d1);
                    d1 = fmaf(qreg[d4 * 4 + 5], k1.y, d1);
                    d1 = fmaf(qreg[d4 * 4 + 6], k1.z, d1);
                    d1 = fmaf(qreg[d4 * 4 + 7], k1.w, d1);
                }
                s[kk] = mv[kk] ? -1e9f : (d0 + d1) * 0.125f;
                tmax = fmaxf(tmax, s[kk]);
            }

            float newm = fmaxf(m, tmax);
            float corr = __expf(m - newm);
            l *= corr;
#pragma unroll
            for (int d = 0; d < D_HEAD; d++) oacc[d] *= corr;

#pragma unroll
            for (int kk = 0; kk < 16; kk++) {
                int krow = c16 * 16 + kk;
                float p = __expf(s[kk] - newm);
                l += p;
#pragma unroll
                for (int d4 = 0; d4 < 16; d4++) {
                    float4 vv = *(const float4*)&Vs[krow][d4 * 4];
                    oacc[d4 * 4 + 0] = fmaf(p, vv.x, oacc[d4 * 4 + 0]);
                    oacc[d4 * 4 + 1] = fmaf(p, vv.y, oacc[d4 * 4 + 1]);
                    oacc[d4 * 4 + 2] = fmaf(p, vv.z, oacc[d4 * 4 + 2]);
                    oacc[d4 * 4 + 3] = fmaf(p, vv.w, oacc[d4 * 4 + 3]);
                }
            }
            m = newm;
        }
    }

    float inv = 1.f / l;
    float* optr = ctx + ((size_t)(b * SEQ + q)) * E_DIM + h * D_HEAD;
#pragma unroll
    for (int d4 = 0; d4 < 16; d4++) {
        float4 o;
        o.x = oacc[d4 * 4 + 0] * inv;
        o.y = oacc[d4 * 4 + 1] * inv;
        o.z = oacc[d4 * 4 + 2] * inv;
        o.w = oacc[d4 * 4 + 3] * inv;
        *(float4*)(optr + d4 * 4) = o;
    }
}

// ---------------------------------------------------------------------------
// In-place LayerNorm over last dim (E=768), one block per row.
// ---------------------------------------------------------------------------
__global__ __launch_bounds__(256) void layernorm_kernel(float* __restrict__ out)
{
    const int row = blockIdx.x;
    const int tid = threadIdx.x;
    float* p = out + (size_t)row * E_DIM;

    float v[3];
    float s = 0.f, sq = 0.f;
#pragma unroll
    for (int i = 0; i < 3; i++) {
        v[i] = p[tid + i * 256];
        s += v[i];
        sq = fmaf(v[i], v[i], sq);
    }

    __shared__ float rs[256], rq[256];
    rs[tid] = s; rq[tid] = sq;
    __syncthreads();
    for (int off = 128; off > 0; off >>= 1) {
        if (tid < off) { rs[tid] += rs[tid + off]; rq[tid] += rq[tid + off]; }
        __syncthreads();
    }
    float mean = rs[0] * (1.f / E_DIM);
    float var  = rq[0] * (1.f / E_DIM) - mean * mean;
    float inv  = rsqrtf(var + 1e-5f);
#pragma unroll
    for (int i = 0; i < 3; i++)
        p[tid + i * 256] = (v[i] - mean) * inv;
}

// ---------------------------------------------------------------------------
extern "C" void kernel_launch(void* const* d_in, const int* in_sizes, int n_in,
                              void* d_out, int out_size)
{
    const float* query = (const float*)d_in[0];
    const float* key   = (const float*)d_in[1];
    const float* value = (const float*)d_in[2];
    const int*   mask  = (const int*)d_in[3];
    const float* Wq = (const float*)d_in[4];
    const float* Wk = (const float*)d_in[5];
    const float* Wv = (const float*)d_in[6];
    const float* Wo = (const float*)d_in[7];
    float* out = (float*)d_out;

    float *pQ, *pK, *pV, *pCtx;
    cudaGetSymbolAddress((void**)&pQ, g_Q);
    cudaGetSymbolAddress((void**)&pK, g_K);
    cudaGetSymbolAddress((void**)&pV, g_V);
    cudaGetSymbolAddress((void**)&pCtx, g_ctx);

    dim3 ggrid(E_DIM / 64, M_ROWS / 64);   // (12, 128)
    gemm_nt_kernel<<<ggrid, 256>>>(query, Wq, nullptr, pQ, 0);
    gemm_nt_kernel<<<ggrid, 256>>>(key,   Wk, nullptr, pK, 0);
    gemm_nt_kernel<<<ggrid, 256>>>(value, Wv, nullptr, pV, 0);

    dim3 agrid(SEQ / 128, N_HEAD, BATCH);  // (16, 12, 4)
    attn_kernel<<<agrid, 128>>>(pQ, pK, pV, mask, pCtx);

    gemm_nt_kernel<<<ggrid, 256>>>(pCtx, Wo, query, out, 1);

    layernorm_kernel<<<M_ROWS, 256>>>(out);
}

// round 4
// speedup vs baseline: 4.1377x; 4.1377x over previous
#include <cuda_runtime.h>
#include <math.h>

#define E_DIM  768
#define N_HEAD 12
#define D_HEAD 64
#define BATCH  4
#define SEQ    2048
#define M_ROWS (BATCH * SEQ)   // 8192

// Scratch (device globals: allocation-free per harness rules)
__device__ float g_Q[BATCH * N_HEAD * SEQ * D_HEAD];
__device__ float g_K[BATCH * N_HEAD * SEQ * D_HEAD];
__device__ float g_V[BATCH * N_HEAD * SEQ * D_HEAD];
__device__ float g_ctx[M_ROWS * E_DIM];
__device__ unsigned int g_mbits[BATCH * SEQ * (SEQ / 32)];   // 2MB bitmask

// ---------------------------------------------------------------------------
__device__ __forceinline__ float tf32r(float x) {
    unsigned int r;
    asm("cvt.rna.tf32.f32 %0, %1;" : "=r"(r) : "f"(x));
    return __uint_as_float(r);
}

__device__ __forceinline__ void mma_tf32(float c[4], const unsigned int a[4],
                                         unsigned int b0, unsigned int b1) {
    asm volatile(
        "mma.sync.aligned.m16n8k8.row.col.f32.tf32.tf32.f32 "
        "{%0,%1,%2,%3}, {%4,%5,%6,%7}, {%8,%9}, {%0,%1,%2,%3};"
        : "+f"(c[0]), "+f"(c[1]), "+f"(c[2]), "+f"(c[3])
        : "r"(a[0]), "r"(a[1]), "r"(a[2]), "r"(a[3]), "r"(b0), "r"(b1));
}

// ---------------------------------------------------------------------------
// mask (int32, nonzero = masked) -> bitmask, 1 word per 32 keys
// ---------------------------------------------------------------------------
__global__ __launch_bounds__(256) void maskbits_kernel(
    const int* __restrict__ mask, unsigned int* __restrict__ bits)
{
    int w = blockIdx.x * 256 + threadIdx.x;      // word index
    const int* p = mask + (size_t)w * 32;
    unsigned int r = 0;
#pragma unroll
    for (int i = 0; i < 8; i++) {
        int4 v = *(const int4*)(p + i * 4);
        if (v.x) r |= 1u << (i * 4 + 0);
        if (v.y) r |= 1u << (i * 4 + 1);
        if (v.z) r |= 1u << (i * 4 + 2);
        if (v.w) r |= 1u << (i * 4 + 3);
    }
    bits[w] = r;
}

// ---------------------------------------------------------------------------
// C[m,n] = sum_k A[m,k] * W[n,k]
// mode 0: scatter into [B,H,S,D] layout, tf32-rounded (QKV projections)
// mode 1: out[m*E+n] = acc + resid[m*E+n] (output projection + residual)
// ---------------------------------------------------------------------------
__global__ __launch_bounds__(256) void gemm_nt_kernel(
    const float* __restrict__ A, const float* __restrict__ W,
    const float* __restrict__ resid, float* __restrict__ out, int mode)
{
    __shared__ __align__(16) float As[16][68];
    __shared__ __align__(16) float Ws[16][68];

    const int tid  = threadIdx.x;
    const int row0 = blockIdx.y * 64;
    const int col0 = blockIdx.x * 64;
    const int lrow = tid >> 2;
    const int kv   = (tid & 3) * 4;
    const int ty   = tid >> 4;
    const int tx   = tid & 15;

    float acc[4][4];
#pragma unroll
    for (int i = 0; i < 4; i++)
#pragma unroll
        for (int j = 0; j < 4; j++) acc[i][j] = 0.f;

    for (int k0 = 0; k0 < E_DIM; k0 += 16) {
        float4 av = *(const float4*)&A[(size_t)(row0 + lrow) * E_DIM + k0 + kv];
        float4 wv = *(const float4*)&W[(size_t)(col0 + lrow) * E_DIM + k0 + kv];
        __syncthreads();
        As[kv + 0][lrow] = av.x; As[kv + 1][lrow] = av.y;
        As[kv + 2][lrow] = av.z; As[kv + 3][lrow] = av.w;
        Ws[kv + 0][lrow] = wv.x; Ws[kv + 1][lrow] = wv.y;
        Ws[kv + 2][lrow] = wv.z; Ws[kv + 3][lrow] = wv.w;
        __syncthreads();
#pragma unroll
        for (int kk = 0; kk < 16; kk++) {
            float4 a = *(const float4*)&As[kk][ty * 4];
            float4 b = *(const float4*)&Ws[kk][tx * 4];
            float ar[4] = {a.x, a.y, a.z, a.w};
            float br[4] = {b.x, b.y, b.z, b.w};
#pragma unroll
            for (int i = 0; i < 4; i++)
#pragma unroll
                for (int j = 0; j < 4; j++)
                    acc[i][j] = fmaf(ar[i], br[j], acc[i][j]);
        }
    }

    if (mode == 0) {
#pragma unroll
        for (int i = 0; i < 4; i++) {
            int m = row0 + ty * 4 + i;
            int b = m >> 11;
            int s = m & (SEQ - 1);
#pragma unroll
            for (int j = 0; j < 4; j++) {
                int n = col0 + tx * 4 + j;
                int h = n >> 6;
                int d = n & (D_HEAD - 1);
                out[(((size_t)b * N_HEAD + h) * SEQ + s) * D_HEAD + d] = tf32r(acc[i][j]);
            }
        }
    } else {
#pragma unroll
        for (int i = 0; i < 4; i++) {
            int m = row0 + ty * 4 + i;
#pragma unroll
            for (int j = 0; j < 4; j++) {
                int n = col0 + tx * 4 + j;
                size_t idx = (size_t)m * E_DIM + n;
                out[idx] = acc[i][j] + resid[idx];
            }
        }
    }
}

// ---------------------------------------------------------------------------
// Flash attention on tensor cores (tf32 m16n8k8).
// Block = 64 queries for one (b,h); 4 warps; each warp: 16 queries.
// K tile 64x64 in smem (stride 68), V tile 64x64 (stride 72) -> conflict-free
// B-fragment loads. Online softmax on C-fragments; P->A transpose via shfl.
// ---------------------------------------------------------------------------
__global__ __launch_bounds__(128, 3) void attn_mma_kernel(
    const float* __restrict__ Q, const float* __restrict__ K,
    const float* __restrict__ V, const unsigned int* __restrict__ mbits,
    float* __restrict__ ctx)
{
    __shared__ __align__(16) float Ks[64][68];
    __shared__ __align__(16) float Vs[64][72];

    const int tid  = threadIdx.x;
    const int warp = tid >> 5;
    const int lane = tid & 31;
    const int g    = lane >> 2;      // groupID
    const int tig  = lane & 3;       // thread-in-group
    const int h    = blockIdx.y;
    const int b    = blockIdx.z;
    const int bh   = b * N_HEAD + h;
    const int q_r0 = blockIdx.x * 64 + warp * 16 + g;   // rows g / g+8
    const int q_r1 = q_r0 + 8;

    const float* Qb = Q + (size_t)bh * SEQ * D_HEAD;
    const float* Kb = K + (size_t)bh * SEQ * D_HEAD;
    const float* Vb = V + (size_t)bh * SEQ * D_HEAD;

    // Q fragments: qa[ks] covers d = ks*8 .. ks*8+7 (A of m16n8k8, row-major)
    unsigned int qa[8][4];
#pragma unroll
    for (int ks = 0; ks < 8; ks++) {
        qa[ks][0] = __float_as_uint(Qb[(size_t)q_r0 * D_HEAD + ks * 8 + tig]);
        qa[ks][1] = __float_as_uint(Qb[(size_t)q_r1 * D_HEAD + ks * 8 + tig]);
        qa[ks][2] = __float_as_uint(Qb[(size_t)q_r0 * D_HEAD + ks * 8 + tig + 4]);
        qa[ks][3] = __float_as_uint(Qb[(size_t)q_r1 * D_HEAD + ks * 8 + tig + 4]);
    }

    float o[8][4];
#pragma unroll
    for (int nt = 0; nt < 8; nt++)
        o[nt][0] = o[nt][1] = o[nt][2] = o[nt][3] = 0.f;
    float m0 = -1e30f, m1 = -1e30f, l0 = 0.f, l1 = 0.f;

    const unsigned int* mrow0 = mbits + ((size_t)b * SEQ + q_r0) * (SEQ / 32);
    const unsigned int* mrow1 = mbits + ((size_t)b * SEQ + q_r1) * (SEQ / 32);

    for (int kt = 0; kt < SEQ / 64; kt++) {
        __syncthreads();
#pragma unroll
        for (int i = 0; i < 8; i++) {
            int idx = tid + i * 128;          // 0..1023
            int r = idx >> 4, c = (idx & 15) << 2;
            *(float4*)&Ks[r][c] = *(const float4*)&Kb[(size_t)(kt * 64 + r) * D_HEAD + c];
            *(float4*)&Vs[r][c] = *(const float4*)&Vb[(size_t)(kt * 64 + r) * D_HEAD + c];
        }
        __syncthreads();

        // --- S = Q @ K^T (16 x 64) ---
        float s[8][4];
#pragma unroll
        for (int nt = 0; nt < 8; nt++) {
            s[nt][0] = s[nt][1] = s[nt][2] = s[nt][3] = 0.f;
#pragma unroll
            for (int ks = 0; ks < 8; ks++) {
                unsigned int b0 = __float_as_uint(Ks[nt * 8 + g][ks * 8 + tig]);
                unsigned int b1 = __float_as_uint(Ks[nt * 8 + g][ks * 8 + tig + 4]);
                mma_tf32(s[nt], qa[ks], b0, b1);
            }
        }

        // --- mask + scale + row max ---
        unsigned int w0a = mrow0[2 * kt], w0b = mrow0[2 * kt + 1];
        unsigned int w1a = mrow1[2 * kt], w1b = mrow1[2 * kt + 1];
        float rmax0 = -1e30f, rmax1 = -1e30f;
#pragma unroll
        for (int nt = 0; nt < 8; nt++) {
            int sh = (nt & 3) * 8 + 2 * tig;
            unsigned int wr0 = (nt < 4) ? w0a : w0b;
            unsigned int wr1 = (nt < 4) ? w1a : w1b;
            s[nt][0] = ((wr0 >> sh) & 1)       ? -1e9f : s[nt][0] * 0.125f;
            s[nt][1] = ((wr0 >> (sh + 1)) & 1) ? -1e9f : s[nt][1] * 0.125f;
            s[nt][2] = ((wr1 >> sh) & 1)       ? -1e9f : s[nt][2] * 0.125f;
            s[nt][3] = ((wr1 >> (sh + 1)) & 1) ? -1e9f : s[nt][3] * 0.125f;
            rmax0 = fmaxf(rmax0, fmaxf(s[nt][0], s[nt][1]));
            rmax1 = fmaxf(rmax1, fmaxf(s[nt][2], s[nt][3]));
        }
        rmax0 = fmaxf(rmax0, __shfl_xor_sync(0xffffffffu, rmax0, 1));
        rmax0 = fmaxf(rmax0, __shfl_xor_sync(0xffffffffu, rmax0, 2));
        rmax1 = fmaxf(rmax1, __shfl_xor_sync(0xffffffffu, rmax1, 1));
        rmax1 = fmaxf(rmax1, __shfl_xor_sync(0xffffffffu, rmax1, 2));

        float mn0 = fmaxf(m0, rmax0), mn1 = fmaxf(m1, rmax1);
        float cr0 = __expf(m0 - mn0), cr1 = __expf(m1 - mn1);
        l0 *= cr0; l1 *= cr1;
        m0 = mn0; m1 = mn1;
#pragma unroll
        for (int nt = 0; nt < 8; nt++) {
            o[nt][0] *= cr0; o[nt][1] *= cr0;
            o[nt][2] *= cr1; o[nt][3] *= cr1;
        }

        // --- P = exp(S - m) ---
#pragma unroll
        for (int nt = 0; nt < 8; nt++) {
            s[nt][0] = __expf(s[nt][0] - m0);
            s[nt][1] = __expf(s[nt][1] - m0);
            s[nt][2] = __expf(s[nt][2] - m1);
            s[nt][3] = __expf(s[nt][3] - m1);
            l0 += s[nt][0] + s[nt][1];
            l1 += s[nt][2] + s[nt][3];
        }

        // --- O += P @ V ---
#pragma unroll
        for (int ks = 0; ks < 8; ks++) {
            int srcA = (lane & ~3) | (tig >> 1);
            int srcB = srcA + 2;
            float x0 = __shfl_sync(0xffffffffu, s[ks][0], srcA);
            float x1 = __shfl_sync(0xffffffffu, s[ks][1], srcA);
            float x2 = __shfl_sync(0xffffffffu, s[ks][0], srcB);
            float x3 = __shfl_sync(0xffffffffu, s[ks][1], srcB);
            float y0 = __shfl_sync(0xffffffffu, s[ks][2], srcA);
            float y1 = __shfl_sync(0xffffffffu, s[ks][3], srcA);
            float y2 = __shfl_sync(0xffffffffu, s[ks][2], srcB);
            float y3 = __shfl_sync(0xffffffffu, s[ks][3], srcB);
            unsigned int pa[4];
            pa[0] = __float_as_uint((tig & 1) ? x1 : x0);
            pa[1] = __float_as_uint((tig & 1) ? y1 : y0);
            pa[2] = __float_as_uint((tig & 1) ? x3 : x2);
            pa[3] = __float_as_uint((tig & 1) ? y3 : y2);
#pragma unroll
            for (int nt = 0; nt < 8; nt++) {
                unsigned int vb0 = __float_as_uint(Vs[ks * 8 + tig][nt * 8 + g]);
                unsigned int vb1 = __float_as_uint(Vs[ks * 8 + tig + 4][nt * 8 + g]);
                mma_tf32(o[nt], pa, vb0, vb1);
            }
        }
    }

    // row-sum reduce across quad, normalize, write [B,S,E]
    l0 += __shfl_xor_sync(0xffffffffu, l0, 1);
    l0 += __shfl_xor_sync(0xffffffffu, l0, 2);
    l1 += __shfl_xor_sync(0xffffffffu, l1, 1);
    l1 += __shfl_xor_sync(0xffffffffu, l1, 2);
    float inv0 = 1.f / l0, inv1 = 1.f / l1;

    float* out0 = ctx + ((size_t)b * SEQ + q_r0) * E_DIM + h * D_HEAD;
    float* out1 = ctx + ((size_t)b * SEQ + q_r1) * E_DIM + h * D_HEAD;
#pragma unroll
    for (int nt = 0; nt < 8; nt++) {
        float2 v0 = make_float2(o[nt][0] * inv0, o[nt][1] * inv0);
        float2 v1 = make_float2(o[nt][2] * inv1, o[nt][3] * inv1);
        *(float2*)&out0[nt * 8 + 2 * tig] = v0;
        *(float2*)&out1[nt * 8 + 2 * tig] = v1;
    }
}

// ---------------------------------------------------------------------------
// In-place LayerNorm over last dim (E=768), one block per row.
// ---------------------------------------------------------------------------
__global__ __launch_bounds__(256) void layernorm_kernel(float* __restrict__ out)
{
    const int row = blockIdx.x;
    const int tid = threadIdx.x;
    float* p = out + (size_t)row * E_DIM;

    float v[3];
    float s = 0.f, sq = 0.f;
#pragma unroll
    for (int i = 0; i < 3; i++) {
        v[i] = p[tid + i * 256];
        s += v[i];
        sq = fmaf(v[i], v[i], sq);
    }

    __shared__ float rs[256], rq[256];
    rs[tid] = s; rq[tid] = sq;
    __syncthreads();
    for (int off = 128; off > 0; off >>= 1) {
        if (tid < off) { rs[tid] += rs[tid + off]; rq[tid] += rq[tid + off]; }
        __syncthreads();
    }
    float mean = rs[0] * (1.f / E_DIM);
    float var  = rq[0] * (1.f / E_DIM) - mean * mean;
    float inv  = rsqrtf(var + 1e-5f);
#pragma unroll
    for (int i = 0; i < 3; i++)
        p[tid + i * 256] = (v[i] - mean) * inv;
}

// ---------------------------------------------------------------------------
extern "C" void kernel_launch(void* const* d_in, const int* in_sizes, int n_in,
                              void* d_out, int out_size)
{
    const float* query = (const float*)d_in[0];
    const float* key   = (const float*)d_in[1];
    const float* value = (const float*)d_in[2];
    const int*   mask  = (const int*)d_in[3];
    const float* Wq = (const float*)d_in[4];
    const float* Wk = (const float*)d_in[5];
    const float* Wv = (const float*)d_in[6];
    const float* Wo = (const float*)d_in[7];
    float* out = (float*)d_out;

    float *pQ, *pK, *pV, *pCtx;
    unsigned int* pBits;
    cudaGetSymbolAddress((void**)&pQ, g_Q);
    cudaGetSymbolAddress((void**)&pK, g_K);
    cudaGetSymbolAddress((void**)&pV, g_V);
    cudaGetSymbolAddress((void**)&pCtx, g_ctx);
    cudaGetSymbolAddress((void**)&pBits, g_mbits);

    maskbits_kernel<<<(BATCH * SEQ * (SEQ / 32)) / 256, 256>>>(mask, pBits);

    dim3 ggrid(E_DIM / 64, M_ROWS / 64);   // (12, 128)
    gemm_nt_kernel<<<ggrid, 256>>>(query, Wq, nullptr, pQ, 0);
    gemm_nt_kernel<<<ggrid, 256>>>(key,   Wk, nullptr, pK, 0);
    gemm_nt_kernel<<<ggrid, 256>>>(value, Wv, nullptr, pV, 0);

    dim3 agrid(SEQ / 64, N_HEAD, BATCH);   // (32, 12, 4)
    attn_mma_kernel<<<agrid, 128>>>(pQ, pK, pV, pBits, pCtx);

    gemm_nt_kernel<<<ggrid, 256>>>(pCtx, Wo, query, out, 1);

    layernorm_kernel<<<M_ROWS, 256>>>(out);
}

// round 5
// speedup vs baseline: 7.4186x; 1.7929x over previous
#include <cuda_runtime.h>
#include <math.h>

#define E_DIM  768
#define N_HEAD 12
#define D_HEAD 64
#define BATCH  4
#define SEQ    2048
#define M_ROWS (BATCH * SEQ)   // 8192

// Scratch (device globals: allocation-free per harness rules)
__device__ float g_Q[BATCH * N_HEAD * SEQ * D_HEAD];
__device__ float g_K[BATCH * N_HEAD * SEQ * D_HEAD];
__device__ float g_V[BATCH * N_HEAD * SEQ * D_HEAD];
__device__ float g_ctx[M_ROWS * E_DIM];
__device__ unsigned int g_mbits[BATCH * SEQ * (SEQ / 32)];   // 2MB bitmask

// ---------------------------------------------------------------------------
__device__ __forceinline__ float tf32r(float x) {
    unsigned int r;
    asm("cvt.rna.tf32.f32 %0, %1;" : "=r"(r) : "f"(x));
    return __uint_as_float(r);
}

__device__ __forceinline__ void mma_tf32(float c[4], const unsigned int a[4],
                                         unsigned int b0, unsigned int b1) {
    asm volatile(
        "mma.sync.aligned.m16n8k8.row.col.f32.tf32.tf32.f32 "
        "{%0,%1,%2,%3}, {%4,%5,%6,%7}, {%8,%9}, {%0,%1,%2,%3};"
        : "+f"(c[0]), "+f"(c[1]), "+f"(c[2]), "+f"(c[3])
        : "r"(a[0]), "r"(a[1]), "r"(a[2]), "r"(a[3]), "r"(b0), "r"(b1));
}

// ---------------------------------------------------------------------------
// mask (int32, nonzero = masked) -> bitmask, 1 word per 32 keys
// ---------------------------------------------------------------------------
__global__ __launch_bounds__(256) void maskbits_kernel(
    const int* __restrict__ mask, unsigned int* __restrict__ bits)
{
    int w = blockIdx.x * 256 + threadIdx.x;      // word index
    const int* p = mask + (size_t)w * 32;
    unsigned int r = 0;
#pragma unroll
    for (int i = 0; i < 8; i++) {
        int4 v = *(const int4*)(p + i * 4);
        if (v.x) r |= 1u << (i * 4 + 0);
        if (v.y) r |= 1u << (i * 4 + 1);
        if (v.z) r |= 1u << (i * 4 + 2);
        if (v.w) r |= 1u << (i * 4 + 3);
    }
    bits[w] = r;
}

// ---------------------------------------------------------------------------
// tf32 tensor-core GEMM:  C[m,n] = sum_k A[m,k] * W[n,k]
// Tile 128x128x32; 8 warps, each 32x64.  A/W tf32-rounded at smem store.
// mode 0: scatter into [B,H,S,D] layout, tf32-rounded (QKV projections)
// mode 1: out[m*E+n] = acc + resid[m*E+n] (output projection + residual)
// ---------------------------------------------------------------------------
#define GBM 128
#define GBN 128
#define GBK 32
#define GSTR 36

__global__ __launch_bounds__(256) void gemm_tf32_kernel(
    const float* __restrict__ A, const float* __restrict__ W,
    const float* __restrict__ resid, float* __restrict__ out, int mode)
{
    __shared__ __align__(16) float As[GBM][GSTR];
    __shared__ __align__(16) float Ws[GBN][GSTR];

    const int tid    = threadIdx.x;
    const int warp   = tid >> 5;
    const int lane   = tid & 31;
    const int g      = lane >> 2;     // groupID 0..7
    const int tig    = lane & 3;      // thread-in-group 0..3
    const int warp_m = warp & 3;      // 4 warps over 128 rows
    const int warp_n = warp >> 2;     // 2 warps over 128 cols
    const int row0   = blockIdx.y * GBM;
    const int col0   = blockIdx.x * GBN;

    const int ldr = tid >> 3;         // 0..31 : not used
    (void)ldr;

    float acc[2][8][4];
#pragma unroll
    for (int mt = 0; mt < 2; mt++)
#pragma unroll
        for (int nt = 0; nt < 8; nt++)
#pragma unroll
            for (int i = 0; i < 4; i++) acc[mt][nt][i] = 0.f;

    for (int k0 = 0; k0 < E_DIM; k0 += GBK) {
        // each thread: 4 float4 of A, 4 float4 of W
        float4 av[4], wv[4];
#pragma unroll
        for (int i = 0; i < 4; i++) {
            int idx = tid + i * 256;          // 0..1023
            int r = idx >> 3, kq = idx & 7;
            av[i] = *(const float4*)&A[(size_t)(row0 + r) * E_DIM + k0 + kq * 4];
            wv[i] = *(const float4*)&W[(size_t)(col0 + r) * E_DIM + k0 + kq * 4];
        }
        __syncthreads();
#pragma unroll
        for (int i = 0; i < 4; i++) {
            int idx = tid + i * 256;
            int r = idx >> 3, kq = idx & 7;
            float4 a = av[i], w = wv[i];
            a.x = tf32r(a.x); a.y = tf32r(a.y); a.z = tf32r(a.z); a.w = tf32r(a.w);
            w.x = tf32r(w.x); w.y = tf32r(w.y); w.z = tf32r(w.z); w.w = tf32r(w.w);
            *(float4*)&As[r][kq * 4] = a;
            *(float4*)&Ws[r][kq * 4] = w;
        }
        __syncthreads();

#pragma unroll
        for (int ks = 0; ks < 4; ks++) {
            const int kk = ks * 8;
            unsigned int af[2][4];
#pragma unroll
            for (int mt = 0; mt < 2; mt++) {
                int m0 = warp_m * 32 + mt * 16;
                af[mt][0] = __float_as_uint(As[m0 + g][kk + tig]);
                af[mt][1] = __float_as_uint(As[m0 + 8 + g][kk + tig]);
                af[mt][2] = __float_as_uint(As[m0 + g][kk + tig + 4]);
                af[mt][3] = __float_as_uint(As[m0 + 8 + g][kk + tig + 4]);
            }
#pragma unroll
            for (int nt = 0; nt < 8; nt++) {
                int n0 = warp_n * 64 + nt * 8;
                unsigned int b0 = __float_as_uint(Ws[n0 + g][kk + tig]);
                unsigned int b1 = __float_as_uint(Ws[n0 + g][kk + tig + 4]);
                mma_tf32(acc[0][nt], af[0], b0, b1);
                mma_tf32(acc[1][nt], af[1], b0, b1);
            }
        }
    }

    if (mode == 0) {
#pragma unroll
        for (int mt = 0; mt < 2; mt++) {
            int mA = row0 + warp_m * 32 + mt * 16 + g;
#pragma unroll
            for (int half = 0; half < 2; half++) {
                int m = mA + half * 8;
                int b = m >> 11;
                int s = m & (SEQ - 1);
#pragma unroll
                for (int nt = 0; nt < 8; nt++) {
                    int n = col0 + warp_n * 64 + nt * 8 + 2 * tig;
                    int h = n >> 6;
                    int d = n & (D_HEAD - 1);
                    float2 v;
                    v.x = tf32r(acc[mt][nt][half * 2 + 0]);
                    v.y = tf32r(acc[mt][nt][half * 2 + 1]);
                    *(float2*)&out[(((size_t)b * N_HEAD + h) * SEQ + s) * D_HEAD + d] = v;
                }
            }
        }
    } else {
#pragma unroll
        for (int mt = 0; mt < 2; mt++) {
            int mA = row0 + warp_m * 32 + mt * 16 + g;
#pragma unroll
            for (int half = 0; half < 2; half++) {
                int m = mA + half * 8;
#pragma unroll
                for (int nt = 0; nt < 8; nt++) {
                    int n = col0 + warp_n * 64 + nt * 8 + 2 * tig;
                    size_t idx = (size_t)m * E_DIM + n;
                    float2 r = *(const float2*)&resid[idx];
                    float2 v;
                    v.x = acc[mt][nt][half * 2 + 0] + r.x;
                    v.y = acc[mt][nt][half * 2 + 1] + r.y;
                    *(float2*)&out[idx] = v;
                }
            }
        }
    }
}

// ---------------------------------------------------------------------------
// Flash attention on tensor cores (tf32 m16n8k8).
// Block = 64 queries for one (b,h); 4 warps; each warp: 16 queries.
// ---------------------------------------------------------------------------
__global__ __launch_bounds__(128, 3) void attn_mma_kernel(
    const float* __restrict__ Q, const float* __restrict__ K,
    const float* __restrict__ V, const unsigned int* __restrict__ mbits,
    float* __restrict__ ctx)
{
    __shared__ __align__(16) float Ks[64][68];
    __shared__ __align__(16) float Vs[64][72];

    const int tid  = threadIdx.x;
    const int warp = tid >> 5;
    const int lane = tid & 31;
    const int g    = lane >> 2;
    const int tig  = lane & 3;
    const int h    = blockIdx.y;
    const int b    = blockIdx.z;
    const int bh   = b * N_HEAD + h;
    const int q_r0 = blockIdx.x * 64 + warp * 16 + g;
    const int q_r1 = q_r0 + 8;

    const float* Qb = Q + (size_t)bh * SEQ * D_HEAD;
    const float* Kb = K + (size_t)bh * SEQ * D_HEAD;
    const float* Vb = V + (size_t)bh * SEQ * D_HEAD;

    unsigned int qa[8][4];
#pragma unroll
    for (int ks = 0; ks < 8; ks++) {
        qa[ks][0] = __float_as_uint(Qb[(size_t)q_r0 * D_HEAD + ks * 8 + tig]);
        qa[ks][1] = __float_as_uint(Qb[(size_t)q_r1 * D_HEAD + ks * 8 + tig]);
        qa[ks][2] = __float_as_uint(Qb[(size_t)q_r0 * D_HEAD + ks * 8 + tig + 4]);
        qa[ks][3] = __float_as_uint(Qb[(size_t)q_r1 * D_HEAD + ks * 8 + tig + 4]);
    }

    float o[8][4];
#pragma unroll
    for (int nt = 0; nt < 8; nt++)
        o[nt][0] = o[nt][1] = o[nt][2] = o[nt][3] = 0.f;
    float m0 = -1e30f, m1 = -1e30f, l0 = 0.f, l1 = 0.f;

    const unsigned int* mrow0 = mbits + ((size_t)b * SEQ + q_r0) * (SEQ / 32);
    const unsigned int* mrow1 = mbits + ((size_t)b * SEQ + q_r1) * (SEQ / 32);

    for (int kt = 0; kt < SEQ / 64; kt++) {
        __syncthreads();
#pragma unroll
        for (int i = 0; i < 8; i++) {
            int idx = tid + i * 128;
            int r = idx >> 4, c = (idx & 15) << 2;
            *(float4*)&Ks[r][c] = *(const float4*)&Kb[(size_t)(kt * 64 + r) * D_HEAD + c];
            *(float4*)&Vs[r][c] = *(const float4*)&Vb[(size_t)(kt * 64 + r) * D_HEAD + c];
        }
        __syncthreads();

        float s[8][4];
#pragma unroll
        for (int nt = 0; nt < 8; nt++) {
            s[nt][0] = s[nt][1] = s[nt][2] = s[nt][3] = 0.f;
#pragma unroll
            for (int ks = 0; ks < 8; ks++) {
                unsigned int b0 = __float_as_uint(Ks[nt * 8 + g][ks * 8 + tig]);
                unsigned int b1 = __float_as_uint(Ks[nt * 8 + g][ks * 8 + tig + 4]);
                mma_tf32(s[nt], qa[ks], b0, b1);
            }
        }

        unsigned int w0a = mrow0[2 * kt], w0b = mrow0[2 * kt + 1];
        unsigned int w1a = mrow1[2 * kt], w1b = mrow1[2 * kt + 1];
        float rmax0 = -1e30f, rmax1 = -1e30f;
#pragma unroll
        for (int nt = 0; nt < 8; nt++) {
            int sh = (nt & 3) * 8 + 2 * tig;
            unsigned int wr0 = (nt < 4) ? w0a : w0b;
            unsigned int wr1 = (nt < 4) ? w1a : w1b;
            s[nt][0] = ((wr0 >> sh) & 1)       ? -1e9f : s[nt][0] * 0.125f;
            s[nt][1] = ((wr0 >> (sh + 1)) & 1) ? -1e9f : s[nt][1] * 0.125f;
            s[nt][2] = ((wr1 >> sh) & 1)       ? -1e9f : s[nt][2] * 0.125f;
            s[nt][3] = ((wr1 >> (sh + 1)) & 1) ? -1e9f : s[nt][3] * 0.125f;
            rmax0 = fmaxf(rmax0, fmaxf(s[nt][0], s[nt][1]));
            rmax1 = fmaxf(rmax1, fmaxf(s[nt][2], s[nt][3]));
        }
        rmax0 = fmaxf(rmax0, __shfl_xor_sync(0xffffffffu, rmax0, 1));
        rmax0 = fmaxf(rmax0, __shfl_xor_sync(0xffffffffu, rmax0, 2));
        rmax1 = fmaxf(rmax1, __shfl_xor_sync(0xffffffffu, rmax1, 1));
        rmax1 = fmaxf(rmax1, __shfl_xor_sync(0xffffffffu, rmax1, 2));

        float mn0 = fmaxf(m0, rmax0), mn1 = fmaxf(m1, rmax1);
        float cr0 = __expf(m0 - mn0), cr1 = __expf(m1 - mn1);
        l0 *= cr0; l1 *= cr1;
        m0 = mn0; m1 = mn1;
#pragma unroll
        for (int nt = 0; nt < 8; nt++) {
            o[nt][0] *= cr0; o[nt][1] *= cr0;
            o[nt][2] *= cr1; o[nt][3] *= cr1;
        }

#pragma unroll
        for (int nt = 0; nt < 8; nt++) {
            s[nt][0] = __expf(s[nt][0] - m0);
            s[nt][1] = __expf(s[nt][1] - m0);
            s[nt][2] = __expf(s[nt][2] - m1);
            s[nt][3] = __expf(s[nt][3] - m1);
            l0 += s[nt][0] + s[nt][1];
            l1 += s[nt][2] + s[nt][3];
        }

#pragma unroll
        for (int ks = 0; ks < 8; ks++) {
            int srcA = (lane & ~3) | (tig >> 1);
            int srcB = srcA + 2;
            float x0 = __shfl_sync(0xffffffffu, s[ks][0], srcA);
            float x1 = __shfl_sync(0xffffffffu, s[ks][1], srcA);
            float x2 = __shfl_sync(0xffffffffu, s[ks][0], srcB);
            float x3 = __shfl_sync(0xffffffffu, s[ks][1], srcB);
            float y0 = __shfl_sync(0xffffffffu, s[ks][2], srcA);
            float y1 = __shfl_sync(0xffffffffu, s[ks][3], srcA);
            float y2 = __shfl_sync(0xffffffffu, s[ks][2], srcB);
            float y3 = __shfl_sync(0xffffffffu, s[ks][3], srcB);
            unsigned int pa[4];
            pa[0] = __float_as_uint((tig & 1) ? x1 : x0);
            pa[1] = __float_as_uint((tig & 1) ? y1 : y0);
            pa[2] = __float_as_uint((tig & 1) ? x3 : x2);
            pa[3] = __float_as_uint((tig & 1) ? y3 : y2);
#pragma unroll
            for (int nt = 0; nt < 8; nt++) {
                unsigned int vb0 = __float_as_uint(Vs[ks * 8 + tig][nt * 8 + g]);
                unsigned int vb1 = __float_as_uint(Vs[ks * 8 + tig + 4][nt * 8 + g]);
                mma_tf32(o[nt], pa, vb0, vb1);
            }
        }
    }

    l0 += __shfl_xor_sync(0xffffffffu, l0, 1);
    l0 += __shfl_xor_sync(0xffffffffu, l0, 2);
    l1 += __shfl_xor_sync(0xffffffffu, l1, 1);
    l1 += __shfl_xor_sync(0xffffffffu, l1, 2);
    float inv0 = 1.f / l0, inv1 = 1.f / l1;

    float* out0 = ctx + ((size_t)b * SEQ + q_r0) * E_DIM + h * D_HEAD;
    float* out1 = ctx + ((size_t)b * SEQ + q_r1) * E_DIM + h * D_HEAD;
#pragma unroll
    for (int nt = 0; nt < 8; nt++) {
        float2 v0 = make_float2(o[nt][0] * inv0, o[nt][1] * inv0);
        float2 v1 = make_float2(o[nt][2] * inv1, o[nt][3] * inv1);
        *(float2*)&out0[nt * 8 + 2 * tig] = v0;
        *(float2*)&out1[nt * 8 + 2 * tig] = v1;
    }
}

// ---------------------------------------------------------------------------
// In-place LayerNorm over last dim (E=768), one block per row.
// ---------------------------------------------------------------------------
__global__ __launch_bounds__(256) void layernorm_kernel(float* __restrict__ out)
{
    const int row = blockIdx.x;
    const int tid = threadIdx.x;
    float* p = out + (size_t)row * E_DIM;

    float v[3];
    float s = 0.f, sq = 0.f;
#pragma unroll
    for (int i = 0; i < 3; i++) {
        v[i] = p[tid + i * 256];
        s += v[i];
        sq = fmaf(v[i], v[i], sq);
    }

    __shared__ float rs[256], rq[256];
    rs[tid] = s; rq[tid] = sq;
    __syncthreads();
    for (int off = 128; off > 0; off >>= 1) {
        if (tid < off) { rs[tid] += rs[tid + off]; rq[tid] += rq[tid + off]; }
        __syncthreads();
    }
    float mean = rs[0] * (1.f / E_DIM);
    float var  = rq[0] * (1.f / E_DIM) - mean * mean;
    float inv  = rsqrtf(var + 1e-5f);
#pragma unroll
    for (int i = 0; i < 3; i++)
        p[tid + i * 256] = (v[i] - mean) * inv;
}

// ---------------------------------------------------------------------------
extern "C" void kernel_launch(void* const* d_in, const int* in_sizes, int n_in,
                              void* d_out, int out_size)
{
    const float* query = (const float*)d_in[0];
    const float* key   = (const float*)d_in[1];
    const float* value = (const float*)d_in[2];
    const int*   mask  = (const int*)d_in[3];
    const float* Wq = (const float*)d_in[4];
    const float* Wk = (const float*)d_in[5];
    const float* Wv = (const float*)d_in[6];
    const float* Wo = (const float*)d_in[7];
    float* out = (float*)d_out;

    float *pQ, *pK, *pV, *pCtx;
    unsigned int* pBits;
    cudaGetSymbolAddress((void**)&pQ, g_Q);
    cudaGetSymbolAddress((void**)&pK, g_K);
    cudaGetSymbolAddress((void**)&pV, g_V);
    cudaGetSymbolAddress((void**)&pCtx, g_ctx);
    cudaGetSymbolAddress((void**)&pBits, g_mbits);

    maskbits_kernel<<<(BATCH * SEQ * (SEQ / 32)) / 256, 256>>>(mask, pBits);

    dim3 ggrid(E_DIM / GBN, M_ROWS / GBM);   // (6, 64)
    gemm_tf32_kernel<<<ggrid, 256>>>(query, Wq, nullptr, pQ, 0);
    gemm_tf32_kernel<<<ggrid, 256>>>(key,   Wk, nullptr, pK, 0);
    gemm_tf32_kernel<<<ggrid, 256>>>(value, Wv, nullptr, pV, 0);

    dim3 agrid(SEQ / 64, N_HEAD, BATCH);   // (32, 12, 4)
    attn_mma_kernel<<<agrid, 128>>>(pQ, pK, pV, pBits, pCtx);

    gemm_tf32_kernel<<<ggrid, 256>>>(pCtx, Wo, query, out, 1);

    layernorm_kernel<<<M_ROWS, 256>>>(out);
}

// round 6
// speedup vs baseline: 8.8200x; 1.1889x over previous
#include <cuda_runtime.h>
#include <math.h>

#define E_DIM  768
#define N_HEAD 12
#define D_HEAD 64
#define BATCH  4
#define SEQ    2048
#define M_ROWS (BATCH * SEQ)   // 8192

// Scratch (device globals: allocation-free per harness rules)
__device__ float g_Q[BATCH * N_HEAD * SEQ * D_HEAD];
__device__ float g_K[BATCH * N_HEAD * SEQ * D_HEAD];
__device__ float g_V[BATCH * N_HEAD * SEQ * D_HEAD];
__device__ float g_ctx[M_ROWS * E_DIM];
__device__ unsigned int g_mbits[BATCH * SEQ * (SEQ / 32)];   // 2MB bitmask

// ---------------------------------------------------------------------------
__device__ __forceinline__ float tf32r(float x) {
    unsigned int r;
    asm("cvt.rna.tf32.f32 %0, %1;" : "=r"(r) : "f"(x));
    return __uint_as_float(r);
}

__device__ __forceinline__ void mma_tf32(float c[4], const unsigned int a[4],
                                         unsigned int b0, unsigned int b1) {
    asm volatile(
        "mma.sync.aligned.m16n8k8.row.col.f32.tf32.tf32.f32 "
        "{%0,%1,%2,%3}, {%4,%5,%6,%7}, {%8,%9}, {%0,%1,%2,%3};"
        : "+f"(c[0]), "+f"(c[1]), "+f"(c[2]), "+f"(c[3])
        : "r"(a[0]), "r"(a[1]), "r"(a[2]), "r"(a[3]), "r"(b0), "r"(b1));
}

__device__ __forceinline__ void cp_async16(const void* smem, const void* gmem) {
    unsigned int s = (unsigned int)__cvta_generic_to_shared(smem);
    asm volatile("cp.async.cg.shared.global [%0], [%1], 16;" :: "r"(s), "l"(gmem));
}
__device__ __forceinline__ void cp_commit() {
    asm volatile("cp.async.commit_group;");
}
template <int N>
__device__ __forceinline__ void cp_wait() {
    asm volatile("cp.async.wait_group %0;" :: "n"(N));
}

// ---------------------------------------------------------------------------
// mask (int32, nonzero = masked) -> bitmask, 1 word per 32 keys
// ---------------------------------------------------------------------------
__global__ __launch_bounds__(256) void maskbits_kernel(
    const int* __restrict__ mask, unsigned int* __restrict__ bits)
{
    int w = blockIdx.x * 256 + threadIdx.x;      // word index
    const int* p = mask + (size_t)w * 32;
    unsigned int r = 0;
#pragma unroll
    for (int i = 0; i < 8; i++) {
        int4 v = *(const int4*)(p + i * 4);
        if (v.x) r |= 1u << (i * 4 + 0);
        if (v.y) r |= 1u << (i * 4 + 1);
        if (v.z) r |= 1u << (i * 4 + 2);
        if (v.w) r |= 1u << (i * 4 + 3);
    }
    bits[w] = r;
}

// ---------------------------------------------------------------------------
// tf32 tensor-core GEMM, cp.async 2-stage pipeline.
// C[m,n] = sum_k A[m,k] * W[n,k].  Tile 128x128x32; 8 warps, each 32x64.
// blockIdx.z selects (A,W,out) triple; mode 0: scatter [B,H,S,D] tf32-rounded;
// mode 1: out = acc + resid.
// ---------------------------------------------------------------------------
#define GBM 128
#define GBN 128
#define GBK 32
#define GSTR 36
#define GEMM_SMEM (2 * 2 * GBM * GSTR * 4)   // 73728 bytes

extern __shared__ float dsm[];

__global__ __launch_bounds__(256) void gemm_tf32_kernel(
    const float* __restrict__ A0, const float* __restrict__ A1, const float* __restrict__ A2,
    const float* __restrict__ W0, const float* __restrict__ W1, const float* __restrict__ W2,
    float* __restrict__ O0, float* __restrict__ O1, float* __restrict__ O2,
    const float* __restrict__ resid, int mode)
{
    float (*As)[GBM][GSTR] = (float (*)[GBM][GSTR])dsm;
    float (*Ws)[GBM][GSTR] = (float (*)[GBM][GSTR])(dsm + 2 * GBM * GSTR);

    const int z = blockIdx.z;
    const float* A = (z == 0) ? A0 : (z == 1) ? A1 : A2;
    const float* W = (z == 0) ? W0 : (z == 1) ? W1 : W2;
    float* out     = (z == 0) ? O0 : (z == 1) ? O1 : O2;

    const int tid    = threadIdx.x;
    const int warp   = tid >> 5;
    const int lane   = tid & 31;
    const int g      = lane >> 2;
    const int tig    = lane & 3;
    const int warp_m = warp & 3;
    const int warp_n = warp >> 2;
    const int row0   = blockIdx.y * GBM;
    const int col0   = blockIdx.x * GBN;

    const int lr = tid >> 3;          // 0..31 row base per i-step? no: full r below
    (void)lr;

    float acc[2][8][4];
#pragma unroll
    for (int mt = 0; mt < 2; mt++)
#pragma unroll
        for (int nt = 0; nt < 8; nt++)
#pragma unroll
            for (int i = 0; i < 4; i++) acc[mt][nt][i] = 0.f;

    // prefetch panel 0 into stage 0
#pragma unroll
    for (int i = 0; i < 4; i++) {
        int idx = tid + i * 256;
        int r = idx >> 3, kq = idx & 7;
        cp_async16(&As[0][r][kq * 4], &A[(size_t)(row0 + r) * E_DIM + kq * 4]);
        cp_async16(&Ws[0][r][kq * 4], &W[(size_t)(col0 + r) * E_DIM + kq * 4]);
    }
    cp_commit();

    int st = 0;
    for (int k0 = 0; k0 < E_DIM; k0 += GBK, st ^= 1) {
        cp_wait<0>();
        __syncthreads();
        if (k0 + GBK < E_DIM) {
#pragma unroll
            for (int i = 0; i < 4; i++) {
                int idx = tid + i * 256;
                int r = idx >> 3, kq = idx & 7;
                cp_async16(&As[st ^ 1][r][kq * 4],
                           &A[(size_t)(row0 + r) * E_DIM + k0 + GBK + kq * 4]);
                cp_async16(&Ws[st ^ 1][r][kq * 4],
                           &W[(size_t)(col0 + r) * E_DIM + k0 + GBK + kq * 4]);
            }
            cp_commit();
        }

#pragma unroll
        for (int ks = 0; ks < 4; ks++) {
            const int kk = ks * 8;
            unsigned int af[2][4];
#pragma unroll
            for (int mt = 0; mt < 2; mt++) {
                int m0 = warp_m * 32 + mt * 16;
                af[mt][0] = __float_as_uint(As[st][m0 + g][kk + tig]);
                af[mt][1] = __float_as_uint(As[st][m0 + 8 + g][kk + tig]);
                af[mt][2] = __float_as_uint(As[st][m0 + g][kk + tig + 4]);
                af[mt][3] = __float_as_uint(As[st][m0 + 8 + g][kk + tig + 4]);
            }
#pragma unroll
            for (int nt = 0; nt < 8; nt++) {
                int n0 = warp_n * 64 + nt * 8;
                unsigned int b0 = __float_as_uint(Ws[st][n0 + g][kk + tig]);
                unsigned int b1 = __float_as_uint(Ws[st][n0 + g][kk + tig + 4]);
                mma_tf32(acc[0][nt], af[0], b0, b1);
                mma_tf32(acc[1][nt], af[1], b0, b1);
            }
        }
        __syncthreads();
    }

    if (mode == 0) {
#pragma unroll
        for (int mt = 0; mt < 2; mt++) {
            int mA = row0 + warp_m * 32 + mt * 16 + g;
#pragma unroll
            for (int half = 0; half < 2; half++) {
                int m = mA + half * 8;
                int b = m >> 11;
                int s = m & (SEQ - 1);
#pragma unroll
                for (int nt = 0; nt < 8; nt++) {
                    int n = col0 + warp_n * 64 + nt * 8 + 2 * tig;
                    int h = n >> 6;
                    int d = n & (D_HEAD - 1);
                    float2 v;
                    v.x = tf32r(acc[mt][nt][half * 2 + 0]);
                    v.y = tf32r(acc[mt][nt][half * 2 + 1]);
                    *(float2*)&out[(((size_t)b * N_HEAD + h) * SEQ + s) * D_HEAD + d] = v;
                }
            }
        }
    } else {
#pragma unroll
        for (int mt = 0; mt < 2; mt++) {
            int mA = row0 + warp_m * 32 + mt * 16 + g;
#pragma unroll
            for (int half = 0; half < 2; half++) {
                int m = mA + half * 8;
#pragma unroll
                for (int nt = 0; nt < 8; nt++) {
                    int n = col0 + warp_n * 64 + nt * 8 + 2 * tig;
                    size_t idx = (size_t)m * E_DIM + n;
                    float2 r = *(const float2*)&resid[idx];
                    float2 v;
                    v.x = acc[mt][nt][half * 2 + 0] + r.x;
                    v.y = acc[mt][nt][half * 2 + 1] + r.y;
                    *(float2*)&out[idx] = v;
                }
            }
        }
    }
}

// ---------------------------------------------------------------------------
// Flash attention on tensor cores (tf32 m16n8k8), cp.async 2-stage K/V pipe.
// Block = 64 queries for one (b,h); 4 warps; each warp: 16 queries.
// ---------------------------------------------------------------------------
#define ATTN_SMEM (2 * 64 * (68 + 72) * 4)   // 71680 bytes

__global__ __launch_bounds__(128, 3) void attn_mma_kernel(
    const float* __restrict__ Q, const float* __restrict__ K,
    const float* __restrict__ V, const unsigned int* __restrict__ mbits,
    float* __restrict__ ctx)
{
    float (*Ks)[64][68] = (float (*)[64][68])dsm;
    float (*Vs)[64][72] = (float (*)[64][72])(dsm + 2 * 64 * 68);

    const int tid  = threadIdx.x;
    const int warp = tid >> 5;
    const int lane = tid & 31;
    const int g    = lane >> 2;
    const int tig  = lane & 3;
    const int h    = blockIdx.y;
    const int b    = blockIdx.z;
    const int bh   = b * N_HEAD + h;
    const int q_r0 = blockIdx.x * 64 + warp * 16 + g;
    const int q_r1 = q_r0 + 8;

    const float* Qb = Q + (size_t)bh * SEQ * D_HEAD;
    const float* Kb = K + (size_t)bh * SEQ * D_HEAD;
    const float* Vb = V + (size_t)bh * SEQ * D_HEAD;

    unsigned int qa[8][4];
#pragma unroll
    for (int ks = 0; ks < 8; ks++) {
        qa[ks][0] = __float_as_uint(Qb[(size_t)q_r0 * D_HEAD + ks * 8 + tig]);
        qa[ks][1] = __float_as_uint(Qb[(size_t)q_r1 * D_HEAD + ks * 8 + tig]);
        qa[ks][2] = __float_as_uint(Qb[(size_t)q_r0 * D_HEAD + ks * 8 + tig + 4]);
        qa[ks][3] = __float_as_uint(Qb[(size_t)q_r1 * D_HEAD + ks * 8 + tig + 4]);
    }

    float o[8][4];
#pragma unroll
    for (int nt = 0; nt < 8; nt++)
        o[nt][0] = o[nt][1] = o[nt][2] = o[nt][3] = 0.f;
    float m0 = -1e30f, m1 = -1e30f, l0 = 0.f, l1 = 0.f;

    const unsigned int* mrow0 = mbits + ((size_t)b * SEQ + q_r0) * (SEQ / 32);
    const unsigned int* mrow1 = mbits + ((size_t)b * SEQ + q_r1) * (SEQ / 32);

    // prefetch tile 0
#pragma unroll
    for (int i = 0; i < 8; i++) {
        int idx = tid + i * 128;
        int r = idx >> 4, c = (idx & 15) << 2;
        cp_async16(&Ks[0][r][c], &Kb[(size_t)r * D_HEAD + c]);
        cp_async16(&Vs[0][r][c], &Vb[(size_t)r * D_HEAD + c]);
    }
    cp_commit();

    int st = 0;
    for (int kt = 0; kt < SEQ / 64; kt++, st ^= 1) {
        cp_wait<0>();
        __syncthreads();
        if (kt + 1 < SEQ / 64) {
#pragma unroll
            for (int i = 0; i < 8; i++) {
                int idx = tid + i * 128;
                int r = idx >> 4, c = (idx & 15) << 2;
                cp_async16(&Ks[st ^ 1][r][c],
                           &Kb[(size_t)((kt + 1) * 64 + r) * D_HEAD + c]);
                cp_async16(&Vs[st ^ 1][r][c],
                           &Vb[(size_t)((kt + 1) * 64 + r) * D_HEAD + c]);
            }
            cp_commit();
        }

        float s[8][4];
#pragma unroll
        for (int nt = 0; nt < 8; nt++) {
            s[nt][0] = s[nt][1] = s[nt][2] = s[nt][3] = 0.f;
#pragma unroll
            for (int ks = 0; ks < 8; ks++) {
                unsigned int b0 = __float_as_uint(Ks[st][nt * 8 + g][ks * 8 + tig]);
                unsigned int b1 = __float_as_uint(Ks[st][nt * 8 + g][ks * 8 + tig + 4]);
                mma_tf32(s[nt], qa[ks], b0, b1);
            }
        }

        unsigned int w0a = mrow0[2 * kt], w0b = mrow0[2 * kt + 1];
        unsigned int w1a = mrow1[2 * kt], w1b = mrow1[2 * kt + 1];
        float rmax0 = -1e30f, rmax1 = -1e30f;
#pragma unroll
        for (int nt = 0; nt < 8; nt++) {
            int sh = (nt & 3) * 8 + 2 * tig;
            unsigned int wr0 = (nt < 4) ? w0a : w0b;
            unsigned int wr1 = (nt < 4) ? w1a : w1b;
            s[nt][0] = ((wr0 >> sh) & 1)       ? -1e9f : s[nt][0] * 0.125f;
            s[nt][1] = ((wr0 >> (sh + 1)) & 1) ? -1e9f : s[nt][1] * 0.125f;
            s[nt][2] = ((wr1 >> sh) & 1)       ? -1e9f : s[nt][2] * 0.125f;
            s[nt][3] = ((wr1 >> (sh + 1)) & 1) ? -1e9f : s[nt][3] * 0.125f;
            rmax0 = fmaxf(rmax0, fmaxf(s[nt][0], s[nt][1]));
            rmax1 = fmaxf(rmax1, fmaxf(s[nt][2], s[nt][3]));
        }
        rmax0 = fmaxf(rmax0, __shfl_xor_sync(0xffffffffu, rmax0, 1));
        rmax0 = fmaxf(rmax0, __shfl_xor_sync(0xffffffffu, rmax0, 2));
        rmax1 = fmaxf(rmax1, __shfl_xor_sync(0xffffffffu, rmax1, 1));
        rmax1 = fmaxf(rmax1, __shfl_xor_sync(0xffffffffu, rmax1, 2));

        float mn0 = fmaxf(m0, rmax0), mn1 = fmaxf(m1, rmax1);
        float cr0 = __expf(m0 - mn0), cr1 = __expf(m1 - mn1);
        l0 *= cr0; l1 *= cr1;
        m0 = mn0; m1 = mn1;
#pragma unroll
        for (int nt = 0; nt < 8; nt++) {
            o[nt][0] *= cr0; o[nt][1] *= cr0;
            o[nt][2] *= cr1; o[nt][3] *= cr1;
        }

#pragma unroll
        for (int nt = 0; nt < 8; nt++) {
            s[nt][0] = __expf(s[nt][0] - m0);
            s[nt][1] = __expf(s[nt][1] - m0);
            s[nt][2] = __expf(s[nt][2] - m1);
            s[nt][3] = __expf(s[nt][3] - m1);
            l0 += s[nt][0] + s[nt][1];
            l1 += s[nt][2] + s[nt][3];
        }

#pragma unroll
        for (int ks = 0; ks < 8; ks++) {
            int srcA = (lane & ~3) | (tig >> 1);
            int srcB = srcA + 2;
            float x0 = __shfl_sync(0xffffffffu, s[ks][0], srcA);
            float x1 = __shfl_sync(0xffffffffu, s[ks][1], srcA);
            float x2 = __shfl_sync(0xffffffffu, s[ks][0], srcB);
            float x3 = __shfl_sync(0xffffffffu, s[ks][1], srcB);
            float y0 = __shfl_sync(0xffffffffu, s[ks][2], srcA);
            float y1 = __shfl_sync(0xffffffffu, s[ks][3], srcA);
            float y2 = __shfl_sync(0xffffffffu, s[ks][2], srcB);
            float y3 = __shfl_sync(0xffffffffu, s[ks][3], srcB);
            unsigned int pa[4];
            pa[0] = __float_as_uint((tig & 1) ? x1 : x0);
            pa[1] = __float_as_uint((tig & 1) ? y1 : y0);
            pa[2] = __float_as_uint((tig & 1) ? x3 : x2);
            pa[3] = __float_as_uint((tig & 1) ? y3 : y2);
#pragma unroll
            for (int nt = 0; nt < 8; nt++) {
                unsigned int vb0 = __float_as_uint(Vs[st][ks * 8 + tig][nt * 8 + g]);
                unsigned int vb1 = __float_as_uint(Vs[st][ks * 8 + tig + 4][nt * 8 + g]);
                mma_tf32(o[nt], pa, vb0, vb1);
            }
        }
        __syncthreads();
    }

    l0 += __shfl_xor_sync(0xffffffffu, l0, 1);
    l0 += __shfl_xor_sync(0xffffffffu, l0, 2);
    l1 += __shfl_xor_sync(0xffffffffu, l1, 1);
    l1 += __shfl_xor_sync(0xffffffffu, l1, 2);
    float inv0 = 1.f / l0, inv1 = 1.f / l1;

    float* out0 = ctx + ((size_t)b * SEQ + q_r0) * E_DIM + h * D_HEAD;
    float* out1 = ctx + ((size_t)b * SEQ + q_r1) * E_DIM + h * D_HEAD;
#pragma unroll
    for (int nt = 0; nt < 8; nt++) {
        float2 v0 = make_float2(o[nt][0] * inv0, o[nt][1] * inv0);
        float2 v1 = make_float2(o[nt][2] * inv1, o[nt][3] * inv1);
        *(float2*)&out0[nt * 8 + 2 * tig] = v0;
        *(float2*)&out1[nt * 8 + 2 * tig] = v1;
    }
}

// ---------------------------------------------------------------------------
// In-place LayerNorm over last dim (E=768), one block per row.
// ---------------------------------------------------------------------------
__global__ __launch_bounds__(256) void layernorm_kernel(float* __restrict__ out)
{
    const int row = blockIdx.x;
    const int tid = threadIdx.x;
    float* p = out + (size_t)row * E_DIM;

    float v[3];
    float s = 0.f, sq = 0.f;
#pragma unroll
    for (int i = 0; i < 3; i++) {
        v[i] = p[tid + i * 256];
        s += v[i];
        sq = fmaf(v[i], v[i], sq);
    }

    __shared__ float rs[256], rq[256];
    rs[tid] = s; rq[tid] = sq;
    __syncthreads();
    for (int off = 128; off > 0; off >>= 1) {
        if (tid < off) { rs[tid] += rs[tid + off]; rq[tid] += rq[tid + off]; }
        __syncthreads();
    }
    float mean = rs[0] * (1.f / E_DIM);
    float var  = rq[0] * (1.f / E_DIM) - mean * mean;
    float inv  = rsqrtf(var + 1e-5f);
#pragma unroll
    for (int i = 0; i < 3; i++)
        p[tid + i * 256] = (v[i] - mean) * inv;
}

// ---------------------------------------------------------------------------
extern "C" void kernel_launch(void* const* d_in, const int* in_sizes, int n_in,
                              void* d_out, int out_size)
{
    const float* query = (const float*)d_in[0];
    const float* key   = (const float*)d_in[1];
    const float* value = (const float*)d_in[2];
    const int*   mask  = (const int*)d_in[3];
    const float* Wq = (const float*)d_in[4];
    const float* Wk = (const float*)d_in[5];
    const float* Wv = (const float*)d_in[6];
    const float* Wo = (const float*)d_in[7];
    float* out = (float*)d_out;

    float *pQ, *pK, *pV, *pCtx;
    unsigned int* pBits;
    cudaGetSymbolAddress((void**)&pQ, g_Q);
    cudaGetSymbolAddress((void**)&pK, g_K);
    cudaGetSymbolAddress((void**)&pV, g_V);
    cudaGetSymbolAddress((void**)&pCtx, g_ctx);
    cudaGetSymbolAddress((void**)&pBits, g_mbits);

    static int attr_done = 0;
    if (!attr_done) {
        cudaFuncSetAttribute(gemm_tf32_kernel,
                             cudaFuncAttributeMaxDynamicSharedMemorySize, GEMM_SMEM);
        cudaFuncSetAttribute(attn_mma_kernel,
                             cudaFuncAttributeMaxDynamicSharedMemorySize, ATTN_SMEM);
        attr_done = 1;
    }

    maskbits_kernel<<<(BATCH * SEQ * (SEQ / 32)) / 256, 256>>>(mask, pBits);

    // fused QKV projections: blockIdx.z selects input/weight/output
    dim3 qkv_grid(E_DIM / GBN, M_ROWS / GBM, 3);   // (6, 64, 3)
    gemm_tf32_kernel<<<qkv_grid, 256, GEMM_SMEM>>>(
        query, key, value, Wq, Wk, Wv, pQ, pK, pV, nullptr, 0);

    dim3 agrid(SEQ / 64, N_HEAD, BATCH);   // (32, 12, 4)
    attn_mma_kernel<<<agrid, 128, ATTN_SMEM>>>(pQ, pK, pV, pBits, pCtx);

    dim3 ogrid(E_DIM / GBN, M_ROWS / GBM, 1);      // (6, 64)
    gemm_tf32_kernel<<<ogrid, 256, GEMM_SMEM>>>(
        pCtx, pCtx, pCtx, Wo, Wo, Wo, out, out, out, query, 1);

    layernorm_kernel<<<M_ROWS, 256>>>(out);
}

// round 15
// speedup vs baseline: 17.4644x; 1.9801x over previous
#include <cuda_runtime.h>
#include <cuda_fp16.h>
#include <math.h>
#include <stdint.h>

#define E_DIM  768
#define N_HEAD 12
#define D_HEAD 64
#define BATCH  4
#define SEQ    2048
#define M_ROWS (BATCH * SEQ)   // 8192

// Scratch (device globals: allocation-free per harness rules)
__device__ __half g_Qh[BATCH * N_HEAD * SEQ * D_HEAD];
__device__ __half g_Kh[BATCH * N_HEAD * SEQ * D_HEAD];
__device__ __half g_Vh[BATCH * N_HEAD * SEQ * D_HEAD];
__device__ __half g_ctxh[M_ROWS * E_DIM];
__device__ __half g_Ah[3][M_ROWS * E_DIM];     // fp16 inputs
__device__ __half g_Wh[4][E_DIM * E_DIM];      // fp16 weights
__device__ unsigned int g_mbits[BATCH * SEQ * (SEQ / 32)];

// ---------------------------------------------------------------------------
__device__ __forceinline__ void mma_f16(float c[4], const uint32_t a[4],
                                        uint32_t b0, uint32_t b1) {
    asm volatile(
        "mma.sync.aligned.m16n8k16.row.col.f32.f16.f16.f32 "
        "{%0,%1,%2,%3}, {%4,%5,%6,%7}, {%8,%9}, {%0,%1,%2,%3};"
        : "+f"(c[0]), "+f"(c[1]), "+f"(c[2]), "+f"(c[3])
        : "r"(a[0]), "r"(a[1]), "r"(a[2]), "r"(a[3]), "r"(b0), "r"(b1));
}

__device__ __forceinline__ void ldsm_x4(uint32_t addr, uint32_t r[4]) {
    asm volatile("ldmatrix.sync.aligned.m8n8.x4.shared.b16 {%0,%1,%2,%3}, [%4];"
                 : "=r"(r[0]), "=r"(r[1]), "=r"(r[2]), "=r"(r[3]) : "r"(addr));
}
__device__ __forceinline__ void ldsm_x4t(uint32_t addr, uint32_t r[4]) {
    asm volatile("ldmatrix.sync.aligned.m8n8.x4.trans.shared.b16 {%0,%1,%2,%3}, [%4];"
                 : "=r"(r[0]), "=r"(r[1]), "=r"(r[2]), "=r"(r[3]) : "r"(addr));
}

__device__ __forceinline__ uint32_t packh2(float lo, float hi) {
    __half2 h = __floats2half2_rn(lo, hi);
    return *(uint32_t*)&h;
}

__device__ __forceinline__ void cp_async16(uint32_t smem, const void* gmem) {
    asm volatile("cp.async.cg.shared.global [%0], [%1], 16;" :: "r"(smem), "l"(gmem));
}
__device__ __forceinline__ void cp_commit() {
    asm volatile("cp.async.commit_group;");
}
template <int N>
__device__ __forceinline__ void cp_wait() {
    asm volatile("cp.async.wait_group %0;" :: "n"(N));
}

extern __shared__ char dynsm[];

// ---------------------------------------------------------------------------
// fp32 -> fp16 conversion passes
// ---------------------------------------------------------------------------
__global__ __launch_bounds__(256) void f2h3_kernel(
    const float* __restrict__ a0, const float* __restrict__ a1,
    const float* __restrict__ a2, __half* __restrict__ o0,
    __half* __restrict__ o1, __half* __restrict__ o2)
{
    int z = blockIdx.y;
    const float* in = (z == 0) ? a0 : (z == 1) ? a1 : a2;
    __half* out     = (z == 0) ? o0 : (z == 1) ? o1 : o2;
    int i = blockIdx.x * 256 + threadIdx.x;
    float4 v = ((const float4*)in)[i];
    __half2 h0 = __floats2half2_rn(v.x, v.y);
    __half2 h1 = __floats2half2_rn(v.z, v.w);
    ((__half2*)out)[2 * i]     = h0;
    ((__half2*)out)[2 * i + 1] = h1;
}

__global__ __launch_bounds__(256) void f2h4_kernel(
    const float* __restrict__ a0, const float* __restrict__ a1,
    const float* __restrict__ a2, const float* __restrict__ a3,
    __half* __restrict__ outbase)
{
    int z = blockIdx.y;
    const float* in = (z == 0) ? a0 : (z == 1) ? a1 : (z == 2) ? a2 : a3;
    __half* out = outbase + (size_t)z * E_DIM * E_DIM;
    int i = blockIdx.x * 256 + threadIdx.x;
    float4 v = ((const float4*)in)[i];
    __half2 h0 = __floats2half2_rn(v.x, v.y);
    __half2 h1 = __floats2half2_rn(v.z, v.w);
    ((__half2*)out)[2 * i]     = h0;
    ((__half2*)out)[2 * i + 1] = h1;
}

// ---------------------------------------------------------------------------
// mask (int32, nonzero = masked) -> bitmask, 1 word per 32 keys
// ---------------------------------------------------------------------------
__global__ __launch_bounds__(256) void maskbits_kernel(
    const int* __restrict__ mask, unsigned int* __restrict__ bits)
{
    int w = blockIdx.x * 256 + threadIdx.x;
    const int* p = mask + (size_t)w * 32;
    unsigned int r = 0;
#pragma unroll
    for (int i = 0; i < 8; i++) {
        int4 v = *(const int4*)(p + i * 4);
        if (v.x) r |= 1u << (i * 4 + 0);
        if (v.y) r |= 1u << (i * 4 + 1);
        if (v.z) r |= 1u << (i * 4 + 2);
        if (v.w) r |= 1u << (i * 4 + 3);
    }
    bits[w] = r;
}

// ---------------------------------------------------------------------------
// fp16 tensor-core GEMM: C[m,n] = sum_k A[m,k] * W[n,k]
// Tile 128x128, K-panel 64, 8 warps each 32x64, ldmatrix fragments,
// cp.async 2-stage pipeline.  Smem rows padded to 72 halves (conflict-free).
// mode 0: half output, scatter [B,H,S,D]; z==0 pre-scales Q by 0.125.
// mode 1: f32 out = acc + resid.
// ---------------------------------------------------------------------------
#define KP      64
#define HSTR    72
#define HSTAGEH (128 * HSTR)                 // halves per matrix per stage
#define GEMM_SMEM_H (2 * 2 * HSTAGEH * 2)    // 73728 bytes

__global__ __launch_bounds__(256) void gemm_h_kernel(
    const __half* __restrict__ A0, const __half* __restrict__ A1, const __half* __restrict__ A2,
    const __half* __restrict__ W0, const __half* __restrict__ W1, const __half* __restrict__ W2,
    __half* __restrict__ H0, __half* __restrict__ H1, __half* __restrict__ H2,
    float* __restrict__ Of, const float* __restrict__ resid, int mode)
{
    const int z = blockIdx.z;
    const __half* A = (z == 0) ? A0 : (z == 1) ? A1 : A2;
    const __half* W = (z == 0) ? W0 : (z == 1) ? W1 : W2;
    __half* Oh      = (z == 0) ? H0 : (z == 1) ? H1 : H2;

    const int tid    = threadIdx.x;
    const int warp   = tid >> 5;
    const int lane   = tid & 31;
    const int g      = lane >> 2;
    const int tig    = lane & 3;
    const int warp_m = warp & 3;
    const int warp_n = warp >> 2;
    const int row0   = blockIdx.y * 128;
    const int col0   = blockIdx.x * 128;

    uint32_t sb = (uint32_t)__cvta_generic_to_shared(dynsm);
    // stage s: A at s*2*HSTAGEH*2 bytes, W at + HSTAGEH*2
    const uint32_t stgb = 2 * HSTAGEH * 2;

    float acc[2][8][4];
#pragma unroll
    for (int mt = 0; mt < 2; mt++)
#pragma unroll
        for (int nt = 0; nt < 8; nt++)
#pragma unroll
            for (int i = 0; i < 4; i++) acc[mt][nt][i] = 0.f;

    auto load_panel = [&](int p, int s) {
#pragma unroll
        for (int i = 0; i < 4; i++) {
            int idx = tid + i * 256;         // 0..1023
            int r = idx >> 3, c8 = idx & 7;
            cp_async16(sb + s * stgb + r * (HSTR * 2) + c8 * 16,
                       &A[(size_t)(row0 + r) * E_DIM + p * KP + c8 * 8]);
            cp_async16(sb + s * stgb + HSTAGEH * 2 + r * (HSTR * 2) + c8 * 16,
                       &W[(size_t)(col0 + r) * E_DIM + p * KP + c8 * 8]);
        }
    };

    load_panel(0, 0);
    cp_commit();

    const int NP = E_DIM / KP;   // 12
    for (int p = 0; p < NP; p++) {
        int s = p & 1;
        cp_wait<0>();
        __syncthreads();
        if (p + 1 < NP) { load_panel(p + 1, s ^ 1); cp_commit(); }

        uint32_t Ab = sb + s * stgb;
        uint32_t Wb = Ab + HSTAGEH * 2;
#pragma unroll
        for (int ks = 0; ks < 4; ks++) {
            uint32_t af[2][4];
#pragma unroll
            for (int mt = 0; mt < 2; mt++) {
                int rowA = warp_m * 32 + mt * 16 + (lane & 15);
                int kofA = ks * 16 + (lane >> 4) * 8;
                ldsm_x4(Ab + (rowA * HSTR + kofA) * 2, af[mt]);
            }
#pragma unroll
            for (int nt2 = 0; nt2 < 4; nt2++) {
                uint32_t bf[4];
                int rowB = warp_n * 64 + nt2 * 16 + (lane >> 4) * 8 + (lane & 7);
                int kofB = ks * 16 + ((lane >> 3) & 1) * 8;
                ldsm_x4(Wb + (rowB * HSTR + kofB) * 2, bf);
                mma_f16(acc[0][2 * nt2],     af[0], bf[0], bf[1]);
                mma_f16(acc[0][2 * nt2 + 1], af[0], bf[2], bf[3]);
                mma_f16(acc[1][2 * nt2],     af[1], bf[0], bf[1]);
                mma_f16(acc[1][2 * nt2 + 1], af[1], bf[2], bf[3]);
            }
        }
        __syncthreads();
    }

    if (mode == 0) {
        const float sc = (z == 0) ? 0.125f : 1.0f;   // fold 1/sqrt(dk) into Q
#pragma unroll
        for (int mt = 0; mt < 2; mt++) {
#pragma unroll
            for (int half_ = 0; half_ < 2; half_++) {
                int m  = row0 + warp_m * 32 + mt * 16 + g + half_ * 8;
                int b  = m >> 11;
                int sq = m & (SEQ - 1);
#pragma unroll
                for (int nt = 0; nt < 8; nt++) {
                    int n = col0 + warp_n * 64 + nt * 8 + 2 * tig;
                    int h = n >> 6;
                    int d = n & (D_HEAD - 1);
                    __half2 v = __floats2half2_rn(acc[mt][nt][half_ * 2 + 0] * sc,
                                                  acc[mt][nt][half_ * 2 + 1] * sc);
                    *(__half2*)&Oh[(((size_t)b * N_HEAD + h) * SEQ + sq) * D_HEAD + d] = v;
                }
            }
        }
    } else {
#pragma unroll
        for (int mt = 0; mt < 2; mt++) {
#pragma unroll
            for (int half_ = 0; half_ < 2; half_++) {
                int m = row0 + warp_m * 32 + mt * 16 + g + half_ * 8;
#pragma unroll
                for (int nt = 0; nt < 8; nt++) {
                    int n = col0 + warp_n * 64 + nt * 8 + 2 * tig;
                    size_t idx = (size_t)m * E_DIM + n;
                    float2 rr = *(const float2*)&resid[idx];
                    float2 v;
                    v.x = acc[mt][nt][half_ * 2 + 0] + rr.x;
                    v.y = acc[mt][nt][half_ * 2 + 1] + rr.y;
                    *(float2*)&Of[idx] = v;
                }
            }
        }
    }
}

// ---------------------------------------------------------------------------
// fp16 flash attention: m16n8k16 mma, ldmatrix K, ldmatrix.trans V,
// P packs directly from softmax registers (no shuffle transpose).
// Block = 64 queries x (b,h); 4 warps; Q pre-scaled by 0.125.
// ---------------------------------------------------------------------------
#define ASTR    72
#define ATILEH  (64 * ASTR)                  // halves per matrix tile
#define ATTN_SMEM_H (2 * 2 * ATILEH * 2)     // 36864 bytes

__global__ __launch_bounds__(128, 3) void attn_h_kernel(
    const __half* __restrict__ Q, const __half* __restrict__ K,
    const __half* __restrict__ V, const unsigned int* __restrict__ mbits,
    __half* __restrict__ ctx)
{
    const int tid  = threadIdx.x;
    const int warp = tid >> 5;
    const int lane = tid & 31;
    const int g    = lane >> 2;
    const int tig  = lane & 3;
    const int h    = blockIdx.y;
    const int b    = blockIdx.z;
    const int bh   = b * N_HEAD + h;
    const int q_r0 = blockIdx.x * 64 + warp * 16 + g;
    const int q_r1 = q_r0 + 8;

    const __half* Qb = Q + (size_t)bh * SEQ * D_HEAD;
    const __half* Kb = K + (size_t)bh * SEQ * D_HEAD;
    const __half* Vb = V + (size_t)bh * SEQ * D_HEAD;

    uint32_t sb = (uint32_t)__cvta_generic_to_shared(dynsm);
    const uint32_t stgb = 2 * ATILEH * 2;    // bytes per stage (K+V)

    // Q fragments: 4 k16 steps, packed half2 (already scaled by 0.125)
    uint32_t qa[4][4];
#pragma unroll
    for (int ks = 0; ks < 4; ks++) {
        qa[ks][0] = *(const uint32_t*)&Qb[(size_t)q_r0 * D_HEAD + ks * 16 + 2 * tig];
        qa[ks][1] = *(const uint32_t*)&Qb[(size_t)q_r1 * D_HEAD + ks * 16 + 2 * tig];
        qa[ks][2] = *(const uint32_t*)&Qb[(size_t)q_r0 * D_HEAD + ks * 16 + 8 + 2 * tig];
        qa[ks][3] = *(const uint32_t*)&Qb[(size_t)q_r1 * D_HEAD + ks * 16 + 8 + 2 * tig];
    }

    float o[8][4];
#pragma unroll
    for (int nt = 0; nt < 8; nt++)
        o[nt][0] = o[nt][1] = o[nt][2] = o[nt][3] = 0.f;
    float m0 = -1e30f, m1 = -1e30f, l0 = 0.f, l1 = 0.f;

    const unsigned int* mrow0 = mbits + ((size_t)b * SEQ + q_r0) * (SEQ / 32);
    const unsigned int* mrow1 = mbits + ((size_t)b * SEQ + q_r1) * (SEQ / 32);

    auto load_tile = [&](int kt, int s) {
#pragma unroll
        for (int i = 0; i < 4; i++) {
            int idx = tid + i * 128;          // 0..511
            int r = idx >> 3, c8 = idx & 7;
            cp_async16(sb + s * stgb + r * (ASTR * 2) + c8 * 16,
                       &Kb[(size_t)(kt * 64 + r) * D_HEAD + c8 * 8]);
            cp_async16(sb + s * stgb + ATILEH * 2 + r * (ASTR * 2) + c8 * 16,
                       &Vb[(size_t)(kt * 64 + r) * D_HEAD + c8 * 8]);
        }
    };

    load_tile(0, 0);
    cp_commit();

    for (int kt = 0; kt < SEQ / 64; kt++) {
        int st = kt & 1;
        cp_wait<0>();
        __syncthreads();
        if (kt + 1 < SEQ / 64) { load_tile(kt + 1, st ^ 1); cp_commit(); }

        uint32_t Kbase = sb + st * stgb;
        uint32_t Vbase = Kbase + ATILEH * 2;

        // --- S = Q @ K^T (16 x 64) ---
        float s[8][4];
#pragma unroll
        for (int nt = 0; nt < 8; nt++)
            s[nt][0] = s[nt][1] = s[nt][2] = s[nt][3] = 0.f;
#pragma unroll
        for (int ks = 0; ks < 4; ks++) {
#pragma unroll
            for (int nt2 = 0; nt2 < 4; nt2++) {
                uint32_t bf[4];
                int rowB = nt2 * 16 + (lane >> 4) * 8 + (lane & 7);
                int kofB = ks * 16 + ((lane >> 3) & 1) * 8;
                ldsm_x4(Kbase + (rowB * ASTR + kofB) * 2, bf);
                mma_f16(s[2 * nt2],     qa[ks], bf[0], bf[1]);
                mma_f16(s[2 * nt2 + 1], qa[ks], bf[2], bf[3]);
            }
        }

        // --- mask + row max (scale already folded into Q) ---
        unsigned int w0a = mrow0[2 * kt], w0b = mrow0[2 * kt + 1];
        unsigned int w1a = mrow1[2 * kt], w1b = mrow1[2 * kt + 1];
        float rmax0 = -1e30f, rmax1 = -1e30f;
#pragma unroll
        for (int nt = 0; nt < 8; nt++) {
            int sh = (nt & 3) * 8 + 2 * tig;
            unsigned int wr0 = (nt < 4) ? w0a : w0b;
            unsigned int wr1 = (nt < 4) ? w1a : w1b;
            if ((wr0 >> sh) & 1)       s[nt][0] = -1e9f;
            if ((wr0 >> (sh + 1)) & 1) s[nt][1] = -1e9f;
            if ((wr1 >> sh) & 1)       s[nt][2] = -1e9f;
            if ((wr1 >> (sh + 1)) & 1) s[nt][3] = -1e9f;
            rmax0 = fmaxf(rmax0, fmaxf(s[nt][0], s[nt][1]));
            rmax1 = fmaxf(rmax1, fmaxf(s[nt][2], s[nt][3]));
        }
        rmax0 = fmaxf(rmax0, __shfl_xor_sync(0xffffffffu, rmax0, 1));
        rmax0 = fmaxf(rmax0, __shfl_xor_sync(0xffffffffu, rmax0, 2));
        rmax1 = fmaxf(rmax1, __shfl_xor_sync(0xffffffffu, rmax1, 1));
        rmax1 = fmaxf(rmax1, __shfl_xor_sync(0xffffffffu, rmax1, 2));

        float mn0 = fmaxf(m0, rmax0), mn1 = fmaxf(m1, rmax1);
        float cr0 = __expf(m0 - mn0), cr1 = __expf(m1 - mn1);
        l0 *= cr0; l1 *= cr1;
        m0 = mn0; m1 = mn1;
#pragma unroll
        for (int nt = 0; nt < 8; nt++) {
            o[nt][0] *= cr0; o[nt][1] *= cr0;
            o[nt][2] *= cr1; o[nt][3] *= cr1;
        }

        // --- P = exp(S - m) ---
#pragma unroll
        for (int nt = 0; nt < 8; nt++) {
            s[nt][0] = __expf(s[nt][0] - m0);
            s[nt][1] = __expf(s[nt][1] - m0);
            s[nt][2] = __expf(s[nt][2] - m1);
            s[nt][3] = __expf(s[nt][3] - m1);
            l0 += s[nt][0] + s[nt][1];
            l1 += s[nt][2] + s[nt][3];
        }

        // --- O += P @ V (P packs directly: C pairs == A k-pairs) ---
#pragma unroll
        for (int kv = 0; kv < 4; kv++) {
            uint32_t pa[4];
            pa[0] = packh2(s[2 * kv][0],     s[2 * kv][1]);
            pa[1] = packh2(s[2 * kv][2],     s[2 * kv][3]);
            pa[2] = packh2(s[2 * kv + 1][0], s[2 * kv + 1][1]);
            pa[3] = packh2(s[2 * kv + 1][2], s[2 * kv + 1][3]);
#pragma unroll
            for (int nt2 = 0; nt2 < 4; nt2++) {
                uint32_t vf[4];
                int rowV = kv * 16 + ((lane >> 3) & 1) * 8 + (lane & 7);
                int colV = nt2 * 16 + (lane >> 4) * 8;
                ldsm_x4t(Vbase + (rowV * ASTR + colV) * 2, vf);
                mma_f16(o[2 * nt2],     pa, vf[0], vf[1]);
                mma_f16(o[2 * nt2 + 1], pa, vf[2], vf[3]);
            }
        }
        __syncthreads();
    }

    l0 += __shfl_xor_sync(0xffffffffu, l0, 1);
    l0 += __shfl_xor_sync(0xffffffffu, l0, 2);
    l1 += __shfl_xor_sync(0xffffffffu, l1, 1);
    l1 += __shfl_xor_sync(0xffffffffu, l1, 2);
    float inv0 = 1.f / l0, inv1 = 1.f / l1;

    __half* out0 = ctx + ((size_t)b * SEQ + q_r0) * E_DIM + h * D_HEAD;
    __half* out1 = ctx + ((size_t)b * SEQ + q_r1) * E_DIM + h * D_HEAD;
#pragma unroll
    for (int nt = 0; nt < 8; nt++) {
        __half2 v0 = __floats2half2_rn(o[nt][0] * inv0, o[nt][1] * inv0);
        __half2 v1 = __floats2half2_rn(o[nt][2] * inv1, o[nt][3] * inv1);
        *(__half2*)&out0[nt * 8 + 2 * tig] = v0;
        *(__half2*)&out1[nt * 8 + 2 * tig] = v1;
    }
}

// ---------------------------------------------------------------------------
// In-place LayerNorm over last dim (E=768), one block per row.
// ---------------------------------------------------------------------------
__global__ __launch_bounds__(256) void layernorm_kernel(float* __restrict__ out)
{
    const int row = blockIdx.x;
    const int tid = threadIdx.x;
    float* p = out + (size_t)row * E_DIM;

    float v[3];
    float s = 0.f, sq = 0.f;
#pragma unroll
    for (int i = 0; i < 3; i++) {
        v[i] = p[tid + i * 256];
        s += v[i];
        sq = fmaf(v[i], v[i], sq);
    }

    __shared__ float rs[256], rq[256];
    rs[tid] = s; rq[tid] = sq;
    __syncthreads();
    for (int off = 128; off > 0; off >>= 1) {
        if (tid < off) { rs[tid] += rs[tid + off]; rq[tid] += rq[tid + off]; }
        __syncthreads();
    }
    float mean = rs[0] * (1.f / E_DIM);
    float var  = rq[0] * (1.f / E_DIM) - mean * mean;
    float inv  = rsqrtf(var + 1e-5f);
#pragma unroll
    for (int i = 0; i < 3; i++)
        p[tid + i * 256] = (v[i] - mean) * inv;
}

// ---------------------------------------------------------------------------
extern "C" void kernel_launch(void* const* d_in, const int* in_sizes, int n_in,
                              void* d_out, int out_size)
{
    const float* query = (const float*)d_in[0];
    const float* key   = (const float*)d_in[1];
    const float* value = (const float*)d_in[2];
    const int*   mask  = (const int*)d_in[3];
    const float* Wq = (const float*)d_in[4];
    const float* Wk = (const float*)d_in[5];
    const float* Wv = (const float*)d_in[6];
    const float* Wo = (const float*)d_in[7];
    float* out = (float*)d_out;

    __half *pQ, *pK, *pV, *pCtx, *pAh, *pWh;
    unsigned int* pBits;
    cudaGetSymbolAddress((void**)&pQ, g_Qh);
    cudaGetSymbolAddress((void**)&pK, g_Kh);
    cudaGetSymbolAddress((void**)&pV, g_Vh);
    cudaGetSymbolAddress((void**)&pCtx, g_ctxh);
    cudaGetSymbolAddress((void**)&pAh, g_Ah);
    cudaGetSymbolAddress((void**)&pWh, g_Wh);
    cudaGetSymbolAddress((void**)&pBits, g_mbits);

    static int attr_done = 0;
    if (!attr_done) {
        cudaFuncSetAttribute(gemm_h_kernel,
                             cudaFuncAttributeMaxDynamicSharedMemorySize, GEMM_SMEM_H);
        cudaFuncSetAttribute(attn_h_kernel,
                             cudaFuncAttributeMaxDynamicSharedMemorySize, ATTN_SMEM_H);
        attr_done = 1;
    }

    maskbits_kernel<<<(BATCH * SEQ * (SEQ / 32)) / 256, 256>>>(mask, pBits);

    // fp32 -> fp16 conversions
    __half* pA0 = pAh;
    __half* pA1 = pAh + (size_t)M_ROWS * E_DIM;
    __half* pA2 = pAh + 2 * (size_t)M_ROWS * E_DIM;
    dim3 c3(M_ROWS * E_DIM / 4 / 256, 3);
    f2h3_kernel<<<c3, 256>>>(query, key, value, pA0, pA1, pA2);
    dim3 c4(E_DIM * E_DIM / 4 / 256, 4);
    f2h4_kernel<<<c4, 256>>>(Wq, Wk, Wv, Wo, pWh);

    // fused QKV projections (z selects input/weight/output); Q pre-scaled
    dim3 qkv_grid(E_DIM / 128, M_ROWS / 128, 3);   // (6, 64, 3)
    gemm_h_kernel<<<qkv_grid, 256, GEMM_SMEM_H>>>(
        pA0, pA1, pA2,
        pWh, pWh + (size_t)E_DIM * E_DIM, pWh + 2 * (size_t)E_DIM * E_DIM,
        pQ, pK, pV, nullptr, nullptr, 0);

    dim3 agrid(SEQ / 64, N_HEAD, BATCH);           // (32, 12, 4)
    attn_h_kernel<<<agrid, 128, ATTN_SMEM_H>>>(pQ, pK, pV, pBits, pCtx);

    // output projection + residual (f32 out)
    dim3 ogrid(E_DIM / 128, M_ROWS / 128, 1);      // (6, 64)
    gemm_h_kernel<<<ogrid, 256, GEMM_SMEM_H>>>(
        pCtx, pCtx, pCtx,
        pWh + 3 * (size_t)E_DIM * E_DIM, pWh + 3 * (size_t)E_DIM * E_DIM,
        pWh + 3 * (size_t)E_DIM * E_DIM,
        nullptr, nullptr, nullptr, out, query, 1);

    layernorm_kernel<<<M_ROWS, 256>>>(out);
}